// round 7
// baseline (speedup 1.0000x reference)
#include <cuda_runtime.h>
#include <cuda_bf16.h>
#include <math.h>
#include <stdint.h>

// Problem constants
#define BB 64
#define TT 1024
#define DD 128
#define HH 256

// Scratch ping-pong buffers [B*T*H] fp32 (64 MB each)
__device__ float g_bufA[(size_t)BB * TT * HH];
__device__ float g_bufB[(size_t)BB * TT * HH];

// ---------------------------------------------------------------------------
// helpers
// ---------------------------------------------------------------------------
__device__ __forceinline__ uint32_t smem_u32(const void* p) {
    uint32_t a;
    asm("{ .reg .u64 t; cvta.to.shared.u64 t, %1; cvt.u32.u64 %0, t; }"
        : "=r"(a) : "l"(p));
    return a;
}

__device__ __forceinline__ void mbar_init(uint32_t addr, uint32_t count) {
    asm volatile("mbarrier.init.shared.b64 [%0], %1;" :: "r"(addr), "r"(count) : "memory");
}

__device__ __forceinline__ void mbar_wait_parity_acq_cluster(uint32_t addr, uint32_t parity) {
    asm volatile(
        "{\n\t"
        ".reg .pred P;\n\t"
        "WAIT_LOOP_%=:\n\t"
        "mbarrier.try_wait.parity.acquire.cluster.shared::cta.b64 P, [%0], %1, 0x989680;\n\t"
        "@!P bra WAIT_LOOP_%=;\n\t"
        "}"
        :: "r"(addr), "r"(parity) : "memory");
}

// ---------------------------------------------------------------------------
// GEMM: C[M,N] = A[M,K] @ W[N,K]^T + b1[n] + b2[n]
// BM=128, BN=128, BK=16, 256 threads, TM=8, TN=8, packed f32x2 accumulators.
// (unchanged from R4)
// ---------------------------------------------------------------------------
__global__ __launch_bounds__(256)
void gemm_bias_kernel(const float* __restrict__ A,
                      const float* __restrict__ W,
                      const float* __restrict__ b1,
                      const float* __restrict__ b2,
                      float* __restrict__ C,
                      int M, int N, int K)
{
    __shared__ float As[16][128];
    __shared__ float Ws[16][128];

    const int m0 = blockIdx.y * 128;
    const int n0 = blockIdx.x * 128;
    const int tid = threadIdx.x;
    const int tr = tid >> 4;
    const int tc = tid & 15;

    uint64_t acc2[8][4];
#pragma unroll
    for (int i = 0; i < 8; i++)
#pragma unroll
        for (int l = 0; l < 4; l++) acc2[i][l] = 0ull;

    for (int k0 = 0; k0 < K; k0 += 16) {
#pragma unroll
        for (int it = 0; it < 2; it++) {
            int id  = tid + it * 256;
            int row = id >> 2;
            int c4  = (id & 3) << 2;
            float4 v = *(const float4*)&A[(size_t)(m0 + row) * K + k0 + c4];
            As[c4 + 0][row] = v.x;
            As[c4 + 1][row] = v.y;
            As[c4 + 2][row] = v.z;
            As[c4 + 3][row] = v.w;
        }
#pragma unroll
        for (int it = 0; it < 2; it++) {
            int id  = tid + it * 256;
            int row = id >> 2;
            int c4  = (id & 3) << 2;
            float4 v = *(const float4*)&W[(size_t)(n0 + row) * K + k0 + c4];
            Ws[c4 + 0][row] = v.x;
            Ws[c4 + 1][row] = v.y;
            Ws[c4 + 2][row] = v.z;
            Ws[c4 + 3][row] = v.w;
        }
        __syncthreads();

#pragma unroll
        for (int k = 0; k < 16; k++) {
            float a[8];
#pragma unroll
            for (int i = 0; i < 8; i++) a[i] = As[k][tr * 8 + i];
            uint64_t w2[4];
            const uint64_t* wp = (const uint64_t*)&Ws[k][tc * 8];
#pragma unroll
            for (int l = 0; l < 4; l++) w2[l] = wp[l];
#pragma unroll
            for (int i = 0; i < 8; i++) {
                uint64_t a2;
                asm("mov.b64 %0, {%1, %1};" : "=l"(a2) : "f"(a[i]));
#pragma unroll
                for (int l = 0; l < 4; l++)
                    asm("fma.rn.f32x2 %0, %1, %2, %0;"
                        : "+l"(acc2[i][l]) : "l"(a2), "l"(w2[l]));
            }
        }
        __syncthreads();
    }

    float bb[8];
#pragma unroll
    for (int l = 0; l < 8; l++) {
        int n = n0 + tc * 8 + l;
        bb[l] = b1[n] + b2[n];
    }
#pragma unroll
    for (int i = 0; i < 8; i++) {
        float r[8];
#pragma unroll
        for (int l = 0; l < 4; l++) {
            uint32_t lo, hi;
            asm("mov.b64 {%0, %1}, %2;" : "=r"(lo), "=r"(hi) : "l"(acc2[i][l]));
            r[2 * l]     = __uint_as_float(lo) + bb[2 * l];
            r[2 * l + 1] = __uint_as_float(hi) + bb[2 * l + 1];
        }
        float* crow = &C[(size_t)(m0 + tr * 8 + i) * N + n0 + tc * 8];
        *(float4*)crow       = make_float4(r[0], r[1], r[2], r[3]);
        *(float4*)(crow + 4) = make_float4(r[4], r[5], r[6], r[7]);
    }
}

// ---------------------------------------------------------------------------
// Recurrence, 2-CTA cluster per batch element. BULK h-exchange.
//   CTA rank r owns outputs j in [r*128, +128). Thread (jl = t0&127, kh = t0>>7)
//   computes the kh-half partial for output j = r*128 + jl.
//     helper (kh == rank): reads locally-written h half; posts red[jl].
//     waiter (kh != rank): waits mbar (peer half delivered by bulk copy),
//       computes peer-half partial, combines, tanh, stores h locally.
//   Publish: ONE elected waiter per CTA sends the CTA's 512B h-half to the
//   peer via cp.async.bulk.shared::cluster (+ remote arrive.expect_tx).
//   mbar: init count 1; per phase = 1 arrival (remote expect) + 512 tx bytes.
// ---------------------------------------------------------------------------
template <bool TRANS>
__global__ __launch_bounds__(256, 1) __cluster_dims__(2, 1, 1)
void rec_cluster_kernel(const float* __restrict__ xw,    // [B, T, H]
                        const float* __restrict__ Whh,   // [H, H]
                        float* __restrict__ out)
{
    __shared__ __align__(16) float hb[2][HH];
    __shared__ float red[128];
    __shared__ __align__(8) uint64_t mbar;

    const int t0 = threadIdx.x;
    const int jl = t0 & 127;
    const int kh = t0 >> 7;
    uint32_t rank;
    asm("mov.u32 %0, %%cluster_ctarank;" : "=r"(rank));
    const int b = blockIdx.x >> 1;
    const int j = (int)rank * 128 + jl;
    const bool waiter = (kh != (int)rank);

    // 128 fp32 weights = 64 packed f32x2 pairs, all in registers.
    uint64_t w[64];
    const uint64_t* wrow = (const uint64_t*)(Whh + (size_t)j * HH + (kh << 7));
#pragma unroll
    for (int i = 0; i < 64; i++) w[i] = wrow[i];

    hb[0][t0] = 0.0f;
    hb[1][t0] = 0.0f;
    const uint32_t mb = smem_u32(&mbar);
    if (t0 == 0) mbar_init(mb, 1);   // 1 arrival (remote expect_tx) per phase
    __syncthreads();
    asm volatile("barrier.cluster.arrive.aligned;" ::: "memory");
    asm volatile("barrier.cluster.wait.aligned;"   ::: "memory");

    const uint32_t peer = rank ^ 1u;
    // Bulk copy: our half [rank*128, +128) of hb[buf] -> same slot in peer CTA.
    const uint32_t s_d0 = smem_u32(&hb[0][(int)rank * 128]);
    const uint32_t s_d1 = smem_u32(&hb[1][(int)rank * 128]);
    uint32_t r_d0, r_d1, r_mb;
    asm("mapa.shared::cluster.u32 %0, %1, %2;" : "=r"(r_d0) : "r"(s_d0), "r"(peer));
    asm("mapa.shared::cluster.u32 %0, %1, %2;" : "=r"(r_d1) : "r"(s_d1), "r"(peer));
    asm("mapa.shared::cluster.u32 %0, %1, %2;" : "=r"(r_mb) : "r"(mb),   "r"(peer));

    const int elect_tid = rank ? 0 : 128;    // first waiter thread
    const float* xp = xw + (size_t)b * TT * HH + j;
    float xin = waiter ? xp[0] : 0.0f;

    int p = 0;
    for (int t = 0; t < TT; ++t) {
        float part;
        if (waiter) {
            if (t) mbar_wait_parity_acq_cluster(mb, (uint32_t)((t - 1) & 1));
        }
        {
            const uint64_t* h2 = (const uint64_t*)(hb[p] + (kh << 7));
            uint64_t a0 = 0ull, a1 = 0ull, a2 = 0ull, a3 = 0ull;
#pragma unroll
            for (int i = 0; i < 64; i += 4) {
                asm("fma.rn.f32x2 %0, %1, %2, %0;" : "+l"(a0) : "l"(w[i + 0]), "l"(h2[i + 0]));
                asm("fma.rn.f32x2 %0, %1, %2, %0;" : "+l"(a1) : "l"(w[i + 1]), "l"(h2[i + 1]));
                asm("fma.rn.f32x2 %0, %1, %2, %0;" : "+l"(a2) : "l"(w[i + 2]), "l"(h2[i + 2]));
                asm("fma.rn.f32x2 %0, %1, %2, %0;" : "+l"(a3) : "l"(w[i + 3]), "l"(h2[i + 3]));
            }
            asm("add.rn.f32x2 %0, %0, %1;" : "+l"(a0) : "l"(a1));
            asm("add.rn.f32x2 %0, %0, %1;" : "+l"(a2) : "l"(a3));
            asm("add.rn.f32x2 %0, %0, %1;" : "+l"(a0) : "l"(a2));
            uint32_t lo, hi;
            asm("mov.b64 {%0, %1}, %2;" : "=r"(lo), "=r"(hi) : "l"(a0));
            part = __uint_as_float(lo) + __uint_as_float(hi);
        }
        float xnext = 0.0f;
        if (waiter) {
            xnext = (t + 1 < TT) ? xp[(size_t)(t + 1) * HH] : 0.0f;
        } else {
            red[jl] = part;
        }
        __syncthreads();   // bar1: red ready; all reads of hb[p] done

        if (waiter) {
            float v = xin + part + red[jl];
            float hval;
            asm("tanh.approx.f32 %0, %1;" : "=f"(hval) : "f"(v));
            hb[p ^ 1][j] = hval;
            __syncthreads();   // bar2: local half of h(t) fully written

            if (t + 1 < TT && t0 == elect_tid) {
                // Order generic STS before async-proxy read, then one bulk
                // copy delivers 512B + completion to the peer's mbar.
                asm volatile("fence.proxy.async.shared::cta;" ::: "memory");
                asm volatile("mbarrier.arrive.expect_tx.release.cluster.shared::cluster.b64 _, [%0], %1;"
                             :: "r"(r_mb), "r"(512u) : "memory");
                asm volatile("cp.async.bulk.shared::cluster.shared::cta.mbarrier::complete_tx::bytes "
                             "[%0], [%1], %2, [%3];"
                             :: "r"(p ? r_d0 : r_d1), "r"(p ? s_d0 : s_d1),
                                "r"(512u), "r"(r_mb) : "memory");
            }
            // Out-store off the critical path.
            if (TRANS) out[((size_t)b * HH + j) * TT + t] = hval;
            else       out[((size_t)b * TT + t) * HH + j] = hval;
            xin = xnext;
        } else {
            __syncthreads();   // bar2 (helpers just pass through)
        }
        p ^= 1;
    }

    asm volatile("barrier.cluster.arrive.aligned;" ::: "memory");
    asm volatile("barrier.cluster.wait.aligned;"   ::: "memory");
}

// ---------------------------------------------------------------------------
// Launch
// ---------------------------------------------------------------------------
extern "C" void kernel_launch(void* const* d_in, const int* in_sizes, int n_in,
                              void* d_out, int out_size)
{
    const float* x     = (const float*)d_in[0];
    const float* W_ih0 = (const float*)d_in[1];
    const float* W_hh0 = (const float*)d_in[2];
    const float* b_ih0 = (const float*)d_in[3];
    const float* b_hh0 = (const float*)d_in[4];
    const float* W_ih1 = (const float*)d_in[5];
    const float* W_hh1 = (const float*)d_in[6];
    const float* b_ih1 = (const float*)d_in[7];
    const float* b_hh1 = (const float*)d_in[8];
    float* out = (float*)d_out;

    float *bufA, *bufB;
    cudaGetSymbolAddress((void**)&bufA, g_bufA);
    cudaGetSymbolAddress((void**)&bufB, g_bufB);

    const int M = BB * TT;  // 65536

    // Layer 1 input projection: bufA = x @ W_ih0^T + (b_ih0 + b_hh0)
    gemm_bias_kernel<<<dim3(HH / 128, M / 128), 256>>>(
        x, W_ih0, b_ih0, b_hh0, bufA, M, HH, DD);

    // Layer 1 recurrence -> bufB = h1 [B,T,H]   (64 clusters of 2 CTAs)
    rec_cluster_kernel<false><<<BB * 2, 256>>>(bufA, W_hh0, bufB);

    // Layer 2 input projection: bufA = h1 @ W_ih1^T + (b_ih1 + b_hh1)
    gemm_bias_kernel<<<dim3(HH / 128, M / 128), 256>>>(
        bufB, W_ih1, b_ih1, b_hh1, bufA, M, HH, HH);

    // Layer 2 recurrence -> out [B,H,T]
    rec_cluster_kernel<true><<<BB * 2, 256>>>(bufA, W_hh1, out);
}